// round 4
// baseline (speedup 1.0000x reference)
#include <cuda_runtime.h>
#include <math.h>

#define BDIM 64
#define SDIM 2048
#define IDIM 512
#define HDIM 512

// Scratch (no cudaMalloc allowed)
__device__ float g_hb[BDIM * HDIM];     // hid + bl + bc
__device__ float g_att[BDIM * SDIM];    // raw attention scores
__device__ float g_cbar[BDIM * IDIM];   // alpha-weighted context sum
__device__ int   g_mask_is_byte;        // 1 if mask is uint8 stream, 0 if int32

// ---------------------------------------------------------------------------
// K0: detect mask storage layout.
// If mask is int32 {0,1}, every byte at index % 4 != 0 is zero.
// If mask is uint8 bool (~50% ones), the first 4KB has nonzero bytes there
// with probability 1 - 2^-3072.
// ---------------------------------------------------------------------------
__global__ void k0_detect(const unsigned char* __restrict__ mraw) {
    __shared__ int found;
    if (threadIdx.x == 0) found = 0;
    __syncthreads();
    int acc = 0;
    for (int i = threadIdx.x; i < 4096; i += 256) {
        if ((i & 3) != 0 && mraw[i] != 0) acc = 1;
    }
    if (acc) atomicOr(&found, 1);
    __syncthreads();
    if (threadIdx.x == 0) g_mask_is_byte = found;
}

// ---------------------------------------------------------------------------
// K1: hb[b,h] = dot(inp[b,:], Wl[h,:]) + bl[h] + bc[h];  also zero g_cbar
// grid(B), block(512)
// ---------------------------------------------------------------------------
__global__ void k1_hb(const float* __restrict__ inp, const float* __restrict__ Wl,
                      const float* __restrict__ bl, const float* __restrict__ bc) {
    __shared__ float sin[IDIM];
    int b = blockIdx.x;
    int h = threadIdx.x;
    sin[h] = inp[b * IDIM + h];
    g_cbar[b * IDIM + h] = 0.0f;
    __syncthreads();
    const float* w = Wl + (size_t)h * IDIM;
    float acc = 0.0f;
    #pragma unroll 8
    for (int i = 0; i < IDIM; i++) acc += w[i] * sin[i];
    g_hb[b * HDIM + h] = acc + bl[h] + bc[h];
}

// ---------------------------------------------------------------------------
// K2: fused ctx-GEMM + tanh + V reduction
//   att[b,s] = sum_h V[h] * tanh( hb[b,h] + sum_i Wc[h,i]*context[b,s,i] )
// Block: 256 threads, tile = 64 s x 64 h, k-step 32, 4x4 per-thread microtile.
// grid(B * S/64)
// ---------------------------------------------------------------------------
#define BM 64
#define BN 64
#define BK 32
#define PAD 4

__global__ __launch_bounds__(256) void k2_att(const float* __restrict__ context,
                                              const float* __restrict__ Wc,
                                              const float* __restrict__ Vv) {
    __shared__ float As[BK][BM + PAD];   // As[k][s]
    __shared__ float Bs[BK][BN + PAD];   // Bs[k][h]
    __shared__ float attred[BM];

    int tid = threadIdx.x;
    int b  = blockIdx.x >> 5;           // S/BM = 32 tiles per batch
    int s0 = (blockIdx.x & 31) * BM;
    int ts = (tid & 15) * 4;            // s offset of this thread's microtile
    int th = (tid >> 4) * 4;            // h offset of this thread's microtile

    const float* ctxb = context + (size_t)b * SDIM * IDIM + (size_t)s0 * IDIM;
    int lrow = tid >> 3;                // 0..31
    int lcol = (tid & 7) * 4;           // 0,4,...,28

    float att_acc[4] = {0.f, 0.f, 0.f, 0.f};

    for (int h0 = 0; h0 < HDIM; h0 += BN) {
        float acc[4][4];
        #pragma unroll
        for (int i = 0; i < 4; i++)
            #pragma unroll
            for (int j = 0; j < 4; j++) acc[i][j] = 0.0f;

        for (int k0 = 0; k0 < IDIM; k0 += BK) {
            // Load context tile [64 s x 32 k], transposed into As[k][s]
            #pragma unroll
            for (int it = 0; it < 2; it++) {
                int row = lrow + it * 32;
                float4 v = *(const float4*)(ctxb + (size_t)row * IDIM + k0 + lcol);
                As[lcol + 0][row] = v.x;
                As[lcol + 1][row] = v.y;
                As[lcol + 2][row] = v.z;
                As[lcol + 3][row] = v.w;
            }
            // Load Wc tile [64 h x 32 k], transposed into Bs[k][h]
            #pragma unroll
            for (int it = 0; it < 2; it++) {
                int row = lrow + it * 32;
                float4 v = *(const float4*)(Wc + (size_t)(h0 + row) * IDIM + k0 + lcol);
                Bs[lcol + 0][row] = v.x;
                Bs[lcol + 1][row] = v.y;
                Bs[lcol + 2][row] = v.z;
                Bs[lcol + 3][row] = v.w;
            }
            __syncthreads();

            #pragma unroll
            for (int k = 0; k < BK; k++) {
                float ra[4], rb[4];
                #pragma unroll
                for (int i = 0; i < 4; i++) ra[i] = As[k][ts + i];
                #pragma unroll
                for (int j = 0; j < 4; j++) rb[j] = Bs[k][th + j];
                #pragma unroll
                for (int i = 0; i < 4; i++)
                    #pragma unroll
                    for (int j = 0; j < 4; j++)
                        acc[i][j] += ra[i] * rb[j];
            }
            __syncthreads();
        }

        // Epilogue for this h-chunk: att += V[h] * tanh(acc + hb)
        #pragma unroll
        for (int j = 0; j < 4; j++) {
            int h = h0 + th + j;
            float vh  = Vv[h];
            float hbv = g_hb[b * HDIM + h];
            #pragma unroll
            for (int i = 0; i < 4; i++)
                att_acc[i] += vh * tanhf(acc[i][j] + hbv);
        }
    }

    // Reduce across the 16 h-thread-groups sharing each s
    if (tid < BM) attred[tid] = 0.0f;
    __syncthreads();
    #pragma unroll
    for (int i = 0; i < 4; i++) atomicAdd(&attred[ts + i], att_acc[i]);
    __syncthreads();
    if (tid < BM) g_att[b * SDIM + s0 + tid] = attred[tid];
}

// ---------------------------------------------------------------------------
// K3: masked softmax over S per batch. alpha written into d_out region.
// grid(B), block(256). Mask layout chosen at runtime via g_mask_is_byte.
// ---------------------------------------------------------------------------
__device__ __forceinline__ bool mask_at(const unsigned char* mraw, int idx, int is_byte) {
    if (is_byte) return mraw[idx] != 0;
    return ((const int*)mraw)[idx] != 0;
}

__global__ void k3_softmax(const unsigned char* __restrict__ mraw,
                           float* __restrict__ alpha) {
    __shared__ float red[256];
    int b = blockIdx.x;
    int tid = threadIdx.x;
    int is_byte = g_mask_is_byte;
    const float NEG_INF = __int_as_float(0xff800000);

    // Pass 1: max of unmasked
    float lmax = NEG_INF;
    for (int s = tid; s < SDIM; s += 256) {
        if (!mask_at(mraw, b * SDIM + s, is_byte))
            lmax = fmaxf(lmax, g_att[b * SDIM + s]);
    }
    red[tid] = lmax;
    __syncthreads();
    for (int o = 128; o > 0; o >>= 1) {
        if (tid < o) red[tid] = fmaxf(red[tid], red[tid + o]);
        __syncthreads();
    }
    float smax = red[0];
    __syncthreads();

    // Pass 2: exp, stash in alpha, accumulate sum
    float lsum = 0.0f;
    for (int s = tid; s < SDIM; s += 256) {
        float e = 0.0f;
        if (!mask_at(mraw, b * SDIM + s, is_byte))
            e = expf(g_att[b * SDIM + s] - smax);
        alpha[b * SDIM + s] = e;
        lsum += e;
    }
    red[tid] = lsum;
    __syncthreads();
    for (int o = 128; o > 0; o >>= 1) {
        if (tid < o) red[tid] += red[tid + o];
        __syncthreads();
    }
    float inv = 1.0f / red[0];
    __syncthreads();

    // Pass 3: normalize
    for (int s = tid; s < SDIM; s += 256) {
        alpha[b * SDIM + s] *= inv;
    }
}

// ---------------------------------------------------------------------------
// K4: cbar[b,i] = sum_s alpha[b,s] * context[b,s,i]   (streaming, 256 MB)
// grid(S/128, B), block(512)
// ---------------------------------------------------------------------------
__global__ void k4_cbar(const float* __restrict__ context,
                        const float* __restrict__ alpha) {
    __shared__ float sal[128];
    int b  = blockIdx.y;
    int s0 = blockIdx.x * 128;
    int i  = threadIdx.x;
    if (i < 128) sal[i] = alpha[b * SDIM + s0 + i];
    __syncthreads();
    const float* cp = context + (size_t)b * SDIM * IDIM + (size_t)s0 * IDIM + i;
    float acc = 0.0f;
    #pragma unroll 4
    for (int s = 0; s < 128; s++) acc += sal[s] * cp[(size_t)s * IDIM];
    atomicAdd(&g_cbar[b * IDIM + i], acc);
}

// ---------------------------------------------------------------------------
// K5: hidden[b,h] = dot(Wc[h,:], cbar[b,:]) + bc[h]
// grid(B), block(512)
// ---------------------------------------------------------------------------
__global__ void k5_out(const float* __restrict__ Wc, const float* __restrict__ bc,
                       float* __restrict__ out) {
    __shared__ float sc[IDIM];
    int b = blockIdx.x;
    int h = threadIdx.x;
    sc[h] = g_cbar[b * IDIM + h];
    __syncthreads();
    const float* w = Wc + (size_t)h * IDIM;
    float acc = bc[h];
    #pragma unroll 8
    for (int i = 0; i < IDIM; i++) acc += w[i] * sc[i];
    out[b * HDIM + h] = acc;
}

// ---------------------------------------------------------------------------
extern "C" void kernel_launch(void* const* d_in, const int* in_sizes, int n_in,
                              void* d_out, int out_size) {
    const float* inp          = (const float*)d_in[0];
    const float* context      = (const float*)d_in[1];
    const unsigned char* mraw = (const unsigned char*)d_in[2];
    const float* Wl           = (const float*)d_in[3];
    const float* bl           = (const float*)d_in[4];
    const float* Wc           = (const float*)d_in[5];
    const float* bc           = (const float*)d_in[6];
    const float* Vv           = (const float*)d_in[7];

    float* out    = (float*)d_out;
    float* hidden = out;                   // [B, HID]
    float* alpha  = out + BDIM * HDIM;     // [B, S]

    k0_detect<<<1, 256>>>(mraw);
    k1_hb<<<BDIM, 512>>>(inp, Wl, bl, bc);
    k2_att<<<BDIM * (SDIM / BM), 256>>>(context, Wc, Vv);
    k3_softmax<<<BDIM, 256>>>(mraw, alpha);
    k4_cbar<<<dim3(SDIM / 128, BDIM), 512>>>(context, alpha);
    k5_out<<<BDIM, 512>>>(Wc, bc, hidden);
}

// round 6
// speedup vs baseline: 2.5895x; 2.5895x over previous
#include <cuda_runtime.h>
#include <cuda_bf16.h>
#include <math.h>
#include <stdint.h>

#define BDIM 64
#define SDIM 2048
#define IDIM 512
#define HDIM 512

// ---------------- device scratch (no cudaMalloc allowed) -------------------
__device__ float g_hb[BDIM * HDIM];      // inp@Wl.T + bl + bc
__device__ float g_att[BDIM * SDIM];     // raw attention scores (accumulated)
__device__ float g_cbar[BDIM * IDIM];    // alpha-weighted context sum
__device__ int   g_mask_is_byte;

__device__ __nv_bfloat16 g_ctx_hi[BDIM * SDIM * IDIM];
__device__ __nv_bfloat16 g_ctx_lo[BDIM * SDIM * IDIM];
__device__ __nv_bfloat16 g_wc_hi[HDIM * IDIM];
__device__ __nv_bfloat16 g_wc_lo[HDIM * IDIM];

// ---------------- PTX helpers (sm_80-level only; no tcgen05) ---------------
__device__ __forceinline__ uint32_t smem_u32(const void* p) {
    uint32_t a;
    asm("{ .reg .u64 t; cvta.to.shared.u64 t, %1; cvt.u32.u64 %0, t; }" : "=r"(a) : "l"(p));
    return a;
}
#define CP16(dst, src) asm volatile("cp.async.cg.shared.global [%0], [%1], 16;" :: "r"(dst), "l"(src))
#define CP_COMMIT()    asm volatile("cp.async.commit_group;" ::: "memory")
#define CP_WAIT(n)     asm volatile("cp.async.wait_group %0;" :: "n"(n) : "memory")

#define LDSM4(r, a)                                                           \
    asm volatile("ldmatrix.sync.aligned.m8n8.x4.shared.b16 {%0,%1,%2,%3}, [%4];" \
        : "=r"((r)[0]), "=r"((r)[1]), "=r"((r)[2]), "=r"((r)[3]) : "r"(a))

#define MMA16816(c, a, b0, b1)                                                \
    asm volatile("mma.sync.aligned.m16n8k16.row.col.f32.bf16.bf16.f32 "       \
        "{%0,%1,%2,%3},{%4,%5,%6,%7},{%8,%9},{%0,%1,%2,%3};"                  \
        : "+f"((c)[0]), "+f"((c)[1]), "+f"((c)[2]), "+f"((c)[3])              \
        : "r"((a)[0]), "r"((a)[1]), "r"((a)[2]), "r"((a)[3]), "r"(b0), "r"(b1))

// ---------------------------------------------------------------------------
// K0: detect mask storage (int32 vs uint8)
// ---------------------------------------------------------------------------
__global__ void k0_detect(const unsigned char* __restrict__ mraw) {
    __shared__ int found;
    if (threadIdx.x == 0) found = 0;
    __syncthreads();
    int acc = 0;
    for (int i = threadIdx.x; i < 4096; i += 256)
        if ((i & 3) != 0 && mraw[i] != 0) acc = 1;
    if (acc) atomicOr(&found, 1);
    __syncthreads();
    if (threadIdx.x == 0) g_mask_is_byte = found;
}

// ---------------------------------------------------------------------------
// Kc: fp32 -> (hi, lo) bf16 split conversion (vectorized float4)
// ---------------------------------------------------------------------------
__global__ void k_conv(const float* __restrict__ src, __nv_bfloat16* __restrict__ hi,
                       __nv_bfloat16* __restrict__ lo, int n4) {
    int i = blockIdx.x * blockDim.x + threadIdx.x;
    if (i >= n4) return;
    float4 v = ((const float4*)src)[i];
    __nv_bfloat16 h0 = __float2bfloat16(v.x), h1 = __float2bfloat16(v.y);
    __nv_bfloat16 h2 = __float2bfloat16(v.z), h3 = __float2bfloat16(v.w);
    __nv_bfloat16 l0 = __float2bfloat16(v.x - __bfloat162float(h0));
    __nv_bfloat16 l1 = __float2bfloat16(v.y - __bfloat162float(h1));
    __nv_bfloat16 l2 = __float2bfloat16(v.z - __bfloat162float(h2));
    __nv_bfloat16 l3 = __float2bfloat16(v.w - __bfloat162float(h3));
    __nv_bfloat162* hp = (__nv_bfloat162*)hi;
    __nv_bfloat162* lp = (__nv_bfloat162*)lo;
    hp[i * 2 + 0] = __nv_bfloat162(h0, h1);
    hp[i * 2 + 1] = __nv_bfloat162(h2, h3);
    lp[i * 2 + 0] = __nv_bfloat162(l0, l1);
    lp[i * 2 + 1] = __nv_bfloat162(l2, l3);
}

// ---------------------------------------------------------------------------
// K1: hb = inp@Wl.T + bl + bc ; zero g_cbar and g_att
// ---------------------------------------------------------------------------
__global__ void k1_hb(const float* __restrict__ inp, const float* __restrict__ Wl,
                      const float* __restrict__ bl, const float* __restrict__ bc) {
    __shared__ float sin[IDIM];
    int b = blockIdx.x;
    int h = threadIdx.x;
    sin[h] = inp[b * IDIM + h];
    g_cbar[b * IDIM + h] = 0.0f;
    #pragma unroll
    for (int j = 0; j < 4; j++) g_att[b * SDIM + j * 512 + h] = 0.0f;
    __syncthreads();
    const float* w = Wl + (size_t)h * IDIM;
    float acc = 0.0f;
    #pragma unroll 8
    for (int i = 0; i < IDIM; i++) acc += w[i] * sin[i];
    g_hb[b * HDIM + h] = acc + bl[h] + bc[h];
}

// ---------------------------------------------------------------------------
// K2: mma.sync bf16 hi/lo-split GEMM + tanh + V reduction
// CTA tile: 128(s) x 128(h), K=512 in 8 chunks of 64; 3-stage cp.async.
// 8 warps, warp tile 64x32 (warp_m = wid&1, warp_n = wid>>1).
// grid = B * 16(stile) * 4(htile) = 4096 CTAs, 256 threads.
// ---------------------------------------------------------------------------
#define STAGE_BYTES 65536        // Ahi 16K | Alo 16K | Bhi 16K | Blo 16K
#define SMEM_K2 (3 * STAGE_BYTES)

__global__ void __launch_bounds__(256, 1) k2_att_mma(const float* __restrict__ Vv) {
    extern __shared__ char smem[];
    __shared__ float sV[128], sHB[128], attred[128];
    uint32_t sb = smem_u32(smem);

    int tid  = threadIdx.x;
    int wid  = tid >> 5;
    int lane = tid & 31;
    int g    = lane >> 2;      // mma group id
    int tg   = lane & 3;       // thread in group
    int warp_m = wid & 1;      // 0..1
    int warp_n = wid >> 1;     // 0..3

    int bx = blockIdx.x;
    int b     = bx >> 6;
    int stile = (bx >> 2) & 15;
    int htile = bx & 3;
    int s0    = stile * 128;
    int hbase = htile * 128;
    int bb    = b * SDIM;

    if (tid < 128) {
        sV[tid]  = Vv[hbase + tid];
        sHB[tid] = g_hb[b * HDIM + hbase + tid];
        attred[tid] = 0.0f;
    }

    // ---- chunk loader: 64 k-values, 128B rows, XOR-swizzled
    auto load_chunk = [&](int kc, int st) {
        int k0 = kc * 64;
        uint32_t base = sb + (uint32_t)st * STAGE_BYTES;
        #pragma unroll
        for (int j = 0; j < 8; j++) {                // A hi+lo: 2048 x 16B
            int idx = j * 256 + tid;
            int sg  = idx >> 10;
            int rem = idx & 1023;
            int r = rem >> 3, c = rem & 7;
            const __nv_bfloat16* src = (sg ? g_ctx_lo : g_ctx_hi)
                + ((size_t)(bb + s0 + r) * IDIM + k0 + c * 8);
            uint32_t o = (uint32_t)(r * 128 + c * 16);
            CP16(base + (uint32_t)sg * 16384u + (o ^ (uint32_t)((r & 7) << 4)), src);
        }
        #pragma unroll
        for (int j = 0; j < 8; j++) {                // B hi+lo: 2048 x 16B
            int idx = j * 256 + tid;
            int sg  = idx >> 10;
            int rem = idx & 1023;
            int r = rem >> 3, c = rem & 7;
            const __nv_bfloat16* src = (sg ? g_wc_lo : g_wc_hi)
                + ((size_t)(hbase + r) * IDIM + k0 + c * 8);
            uint32_t o = (uint32_t)(r * 128 + c * 16);
            CP16(base + 32768u + (uint32_t)sg * 16384u + (o ^ (uint32_t)((r & 7) << 4)), src);
        }
        CP_COMMIT();
    };

    // ---- per-thread ldmatrix address components
    int arow  = warp_m * 64 + (lane & 15);
    uint32_t akoff = (uint32_t)(lane & 16);          // 0 or 16
    uint32_t axor  = (uint32_t)((lane & 7) << 4);
    int brow  = (lane & 7) + ((lane & 16) >> 1);     // 0..15
    uint32_t bkoff = (uint32_t)(((lane >> 3) & 1) * 16);
    uint32_t bxor  = axor;

    uint32_t aoff[4], boff[2];
    #pragma unroll
    for (int t = 0; t < 4; t++) aoff[t] = (uint32_t)((arow + t * 16) * 128) + akoff;
    #pragma unroll
    for (int p = 0; p < 2; p++) boff[p] = (uint32_t)((warp_n * 32 + p * 16 + brow) * 128) + bkoff;

    float acc[4][4][4];
    #pragma unroll
    for (int t = 0; t < 4; t++)
        #pragma unroll
        for (int n = 0; n < 4; n++)
            #pragma unroll
            for (int c = 0; c < 4; c++) acc[t][n][c] = 0.0f;

    load_chunk(0, 0);
    load_chunk(1, 1);

    #pragma unroll 1
    for (int i = 0; i < 8; i++) {
        if (i + 2 < 8) load_chunk(i + 2, (i + 2) % 3);
        if (i + 2 < 8)      { CP_WAIT(2); }
        else if (i + 1 < 8) { CP_WAIT(1); }
        else                { CP_WAIT(0); }
        __syncthreads();

        uint32_t stb = sb + (uint32_t)(i % 3) * STAGE_BYTES;
        uint32_t Ahi = stb, Alo = stb + 16384u, Bhi = stb + 32768u, Blo = stb + 49152u;

        #pragma unroll
        for (int q = 0; q < 4; q++) {
            uint32_t qb = (uint32_t)(q * 32);
            uint32_t aH[4][4], aL[4][4], bH[2][4], bL[2][4];
            #pragma unroll
            for (int t = 0; t < 4; t++) {
                LDSM4(aH[t], Ahi + ((aoff[t] + qb) ^ axor));
                LDSM4(aL[t], Alo + ((aoff[t] + qb) ^ axor));
            }
            #pragma unroll
            for (int p = 0; p < 2; p++) {
                LDSM4(bH[p], Bhi + ((boff[p] + qb) ^ bxor));
                LDSM4(bL[p], Blo + ((boff[p] + qb) ^ bxor));
            }
            #pragma unroll
            for (int t = 0; t < 4; t++) {
                #pragma unroll
                for (int nt = 0; nt < 4; nt++) {
                    int p  = nt >> 1;
                    int r0 = (nt & 1) * 2;
                    MMA16816(acc[t][nt], aH[t], bH[p][r0], bH[p][r0 + 1]);
                    MMA16816(acc[t][nt], aH[t], bL[p][r0], bL[p][r0 + 1]);
                    MMA16816(acc[t][nt], aL[t], bH[p][r0], bH[p][r0 + 1]);
                }
            }
        }
        __syncthreads();
    }

    // ---- epilogue: att[s] += sum_h V[h]*tanh(acc + hb[h])
    float rowsum[8];
    #pragma unroll
    for (int r = 0; r < 8; r++) rowsum[r] = 0.0f;
    #pragma unroll
    for (int t = 0; t < 4; t++) {
        #pragma unroll
        for (int nt = 0; nt < 4; nt++) {
            int hh = warp_n * 32 + nt * 8 + tg * 2;
            float v0 = sV[hh], v1 = sV[hh + 1];
            float h0 = sHB[hh], h1 = sHB[hh + 1];
            float* c = acc[t][nt];
            rowsum[t * 2 + 0] += v0 * tanhf(c[0] + h0) + v1 * tanhf(c[1] + h1);
            rowsum[t * 2 + 1] += v0 * tanhf(c[2] + h0) + v1 * tanhf(c[3] + h1);
        }
    }
    #pragma unroll
    for (int r = 0; r < 8; r++) {
        float s = rowsum[r];
        s += __shfl_xor_sync(0xffffffffu, s, 1);
        s += __shfl_xor_sync(0xffffffffu, s, 2);
        if (tg == 0) {
            int row = warp_m * 64 + (r >> 1) * 16 + (r & 1) * 8 + g;
            atomicAdd(&attred[row], s);
        }
    }
    __syncthreads();
    if (tid < 128) atomicAdd(&g_att[b * SDIM + s0 + tid], attred[tid]);
}

// ---------------------------------------------------------------------------
// K3: masked softmax over S per batch -> alpha
// ---------------------------------------------------------------------------
__device__ __forceinline__ bool mask_at(const unsigned char* m, int idx, int is_byte) {
    if (is_byte) return m[idx] != 0;
    return ((const int*)m)[idx] != 0;
}

__global__ void k3_softmax(const unsigned char* __restrict__ mraw,
                           float* __restrict__ alpha) {
    __shared__ float red[256];
    int b = blockIdx.x;
    int tid = threadIdx.x;
    int is_byte = g_mask_is_byte;
    const float NEG_INF = __int_as_float(0xff800000);

    float lmax = NEG_INF;
    for (int s = tid; s < SDIM; s += 256)
        if (!mask_at(mraw, b * SDIM + s, is_byte))
            lmax = fmaxf(lmax, g_att[b * SDIM + s]);
    red[tid] = lmax;
    __syncthreads();
    for (int o = 128; o > 0; o >>= 1) {
        if (tid < o) red[tid] = fmaxf(red[tid], red[tid + o]);
        __syncthreads();
    }
    float smax = red[0];
    __syncthreads();

    float lsum = 0.0f;
    for (int s = tid; s < SDIM; s += 256) {
        float e = 0.0f;
        if (!mask_at(mraw, b * SDIM + s, is_byte))
            e = expf(g_att[b * SDIM + s] - smax);
        alpha[b * SDIM + s] = e;
        lsum += e;
    }
    red[tid] = lsum;
    __syncthreads();
    for (int o = 128; o > 0; o >>= 1) {
        if (tid < o) red[tid] += red[tid + o];
        __syncthreads();
    }
    float inv = 1.0f / red[0];
    __syncthreads();

    for (int s = tid; s < SDIM; s += 256)
        alpha[b * SDIM + s] *= inv;
}

// ---------------------------------------------------------------------------
// K4: cbar[b,i] = sum_s alpha[b,s] * context[b,s,i]  (streams 256 MB)
// ---------------------------------------------------------------------------
__global__ void k4_cbar(const float* __restrict__ context,
                        const float* __restrict__ alpha) {
    __shared__ float sal[128];
    int b  = blockIdx.y;
    int s0 = blockIdx.x * 128;
    int i  = threadIdx.x;
    if (i < 128) sal[i] = alpha[b * SDIM + s0 + i];
    __syncthreads();
    const float* cp = context + (size_t)b * SDIM * IDIM + (size_t)s0 * IDIM + i;
    float acc = 0.0f;
    #pragma unroll 4
    for (int s = 0; s < 128; s++) acc += sal[s] * cp[(size_t)s * IDIM];
    atomicAdd(&g_cbar[b * IDIM + i], acc);
}

// ---------------------------------------------------------------------------
// K5: hidden = Wc @ cbar + bc
// ---------------------------------------------------------------------------
__global__ void k5_out(const float* __restrict__ Wc, const float* __restrict__ bc,
                       float* __restrict__ out) {
    __shared__ float sc[IDIM];
    int b = blockIdx.x;
    int h = threadIdx.x;
    sc[h] = g_cbar[b * IDIM + h];
    __syncthreads();
    const float* w = Wc + (size_t)h * IDIM;
    float acc = bc[h];
    #pragma unroll 8
    for (int i = 0; i < IDIM; i++) acc += w[i] * sc[i];
    out[b * HDIM + h] = acc;
}

// ---------------------------------------------------------------------------
extern "C" void kernel_launch(void* const* d_in, const int* in_sizes, int n_in,
                              void* d_out, int out_size) {
    const float* inp          = (const float*)d_in[0];
    const float* context      = (const float*)d_in[1];
    const unsigned char* mraw = (const unsigned char*)d_in[2];
    const float* Wl           = (const float*)d_in[3];
    const float* bl           = (const float*)d_in[4];
    const float* Wc           = (const float*)d_in[5];
    const float* bc           = (const float*)d_in[6];
    const float* Vv           = (const float*)d_in[7];

    float* out    = (float*)d_out;
    float* hidden = out;                   // [B, HID]
    float* alpha  = out + BDIM * HDIM;     // [B, S]

    cudaFuncSetAttribute(k2_att_mma, cudaFuncAttributeMaxDynamicSharedMemorySize, SMEM_K2);

    __nv_bfloat16 *ctx_hi, *ctx_lo, *wc_hi, *wc_lo;
    cudaGetSymbolAddress((void**)&ctx_hi, g_ctx_hi);
    cudaGetSymbolAddress((void**)&ctx_lo, g_ctx_lo);
    cudaGetSymbolAddress((void**)&wc_hi, g_wc_hi);
    cudaGetSymbolAddress((void**)&wc_lo, g_wc_lo);

    k0_detect<<<1, 256>>>(mraw);
    int n4c = BDIM * SDIM * IDIM / 4;
    k_conv<<<n4c / 256, 256>>>(context, ctx_hi, ctx_lo, n4c);
    int n4w = HDIM * IDIM / 4;
    k_conv<<<n4w / 256, 256>>>(Wc, wc_hi, wc_lo, n4w);
    k1_hb<<<BDIM, 512>>>(inp, Wl, bl, bc);
    k2_att_mma<<<BDIM * 16 * 4, 256, SMEM_K2>>>(Vv);
    k3_softmax<<<BDIM, 256>>>(mraw, alpha);
    k4_cbar<<<dim3(SDIM / 128, BDIM), 512>>>(context, alpha);
    k5_out<<<BDIM, 512>>>(Wc, bc, hidden);
}

// round 7
// speedup vs baseline: 3.4677x; 1.3391x over previous
#include <cuda_runtime.h>
#include <cuda_bf16.h>
#include <math.h>
#include <stdint.h>

#define BDIM 64
#define SDIM 2048
#define IDIM 512
#define HDIM 512

// ---------------- device scratch (no cudaMalloc allowed) -------------------
__device__ float g_hb[BDIM * HDIM];      // inp@Wl.T + bl + bc
__device__ float g_att[BDIM * SDIM];     // raw attention scores (accumulated)
__device__ float g_cbar[BDIM * IDIM];    // alpha-weighted context sum
__device__ int   g_mask_is_byte;

__device__ __nv_bfloat16 g_ctx_hi[BDIM * SDIM * IDIM];
__device__ __nv_bfloat16 g_ctx_lo[BDIM * SDIM * IDIM];
__device__ __nv_bfloat16 g_wc_hi[HDIM * IDIM];
__device__ __nv_bfloat16 g_wc_lo[HDIM * IDIM];

// ---------------- PTX helpers (sm_80-level only; no tcgen05) ---------------
__device__ __forceinline__ uint32_t smem_u32(const void* p) {
    uint32_t a;
    asm("{ .reg .u64 t; cvta.to.shared.u64 t, %1; cvt.u32.u64 %0, t; }" : "=r"(a) : "l"(p));
    return a;
}
#define CP16(dst, src) asm volatile("cp.async.cg.shared.global [%0], [%1], 16;" :: "r"(dst), "l"(src))
#define CP_COMMIT()    asm volatile("cp.async.commit_group;" ::: "memory")
#define CP_WAIT(n)     asm volatile("cp.async.wait_group %0;" :: "n"(n) : "memory")

#define LDSM4(r, a)                                                           \
    asm volatile("ldmatrix.sync.aligned.m8n8.x4.shared.b16 {%0,%1,%2,%3}, [%4];" \
        : "=r"((r)[0]), "=r"((r)[1]), "=r"((r)[2]), "=r"((r)[3]) : "r"(a))

#define MMA16816(c, a, b0, b1)                                                \
    asm volatile("mma.sync.aligned.m16n8k16.row.col.f32.bf16.bf16.f32 "       \
        "{%0,%1,%2,%3},{%4,%5,%6,%7},{%8,%9},{%0,%1,%2,%3};"                  \
        : "+f"((c)[0]), "+f"((c)[1]), "+f"((c)[2]), "+f"((c)[3])              \
        : "r"((a)[0]), "r"((a)[1]), "r"((a)[2]), "r"((a)[3]), "r"(b0), "r"(b1))

// ---------------------------------------------------------------------------
// K0: detect mask storage (int32 vs uint8)
// ---------------------------------------------------------------------------
__global__ void k0_detect(const unsigned char* __restrict__ mraw) {
    __shared__ int found;
    if (threadIdx.x == 0) found = 0;
    __syncthreads();
    int acc = 0;
    for (int i = threadIdx.x; i < 4096; i += 256)
        if ((i & 3) != 0 && mraw[i] != 0) acc = 1;
    if (acc) atomicOr(&found, 1);
    __syncthreads();
    if (threadIdx.x == 0) g_mask_is_byte = found;
}

// ---------------------------------------------------------------------------
// Kc: fp32 -> (hi, lo) bf16 split conversion (vectorized float4)
// ---------------------------------------------------------------------------
__global__ void k_conv(const float* __restrict__ src, __nv_bfloat16* __restrict__ hi,
                       __nv_bfloat16* __restrict__ lo, int n4) {
    int i = blockIdx.x * blockDim.x + threadIdx.x;
    if (i >= n4) return;
    float4 v = ((const float4*)src)[i];
    __nv_bfloat16 h0 = __float2bfloat16(v.x), h1 = __float2bfloat16(v.y);
    __nv_bfloat16 h2 = __float2bfloat16(v.z), h3 = __float2bfloat16(v.w);
    __nv_bfloat16 l0 = __float2bfloat16(v.x - __bfloat162float(h0));
    __nv_bfloat16 l1 = __float2bfloat16(v.y - __bfloat162float(h1));
    __nv_bfloat16 l2 = __float2bfloat16(v.z - __bfloat162float(h2));
    __nv_bfloat16 l3 = __float2bfloat16(v.w - __bfloat162float(h3));
    __nv_bfloat162* hp = (__nv_bfloat162*)hi;
    __nv_bfloat162* lp = (__nv_bfloat162*)lo;
    hp[i * 2 + 0] = __nv_bfloat162(h0, h1);
    hp[i * 2 + 1] = __nv_bfloat162(h2, h3);
    lp[i * 2 + 0] = __nv_bfloat162(l0, l1);
    lp[i * 2 + 1] = __nv_bfloat162(l2, l3);
}

// ---------------------------------------------------------------------------
// K1: hb = inp@Wl.T + bl + bc ; zero g_cbar and g_att
// grid(B*4) -- block handles 128 h rows. Warp-per-row, coalesced float4 reads,
// shfl butterfly reduction (fixes the 32-way L1 replay of the old version).
// ---------------------------------------------------------------------------
__global__ void __launch_bounds__(256) k1_hb(const float* __restrict__ inp,
                                             const float* __restrict__ Wl,
                                             const float* __restrict__ bl,
                                             const float* __restrict__ bc) {
    __shared__ float sin[IDIM];
    int b  = blockIdx.x >> 2;
    int hq = blockIdx.x & 3;           // h quarter (128 rows)
    int tid = threadIdx.x;
    int wid = tid >> 5, lane = tid & 31;

    sin[tid] = inp[b * IDIM + tid];
    sin[tid + 256] = inp[b * IDIM + tid + 256];
    // zero scratch
    g_att[b * SDIM + hq * 512 + tid * 2 + 0] = 0.0f;
    g_att[b * SDIM + hq * 512 + tid * 2 + 1] = 0.0f;
    if (tid < 128) g_cbar[b * IDIM + hq * 128 + tid] = 0.0f;
    __syncthreads();

    const float4* s4 = (const float4*)sin;
    #pragma unroll 1
    for (int r = wid; r < 128; r += 8) {
        int h = hq * 128 + r;
        const float4* w4 = (const float4*)(Wl + (size_t)h * IDIM);
        float acc = 0.0f;
        #pragma unroll
        for (int j = 0; j < 4; j++) {
            float4 w = w4[lane + 32 * j];
            float4 s = s4[lane + 32 * j];
            acc += w.x * s.x + w.y * s.y + w.z * s.z + w.w * s.w;
        }
        #pragma unroll
        for (int o = 16; o > 0; o >>= 1) acc += __shfl_xor_sync(0xffffffffu, acc, o);
        if (lane == 0) g_hb[b * HDIM + h] = acc + bl[h] + bc[h];
    }
}

// ---------------------------------------------------------------------------
// K2: mma.sync bf16 hi/lo-split GEMM + tanh + V reduction
// CTA tile: 128(s) x 128(h), K=512 in 8 chunks of 64; 3-stage cp.async.
// 8 warps, warp tile 64x32 (warp_m = wid&1, warp_n = wid>>1).
// grid = B * 16(stile) * 4(htile) = 4096 CTAs, 256 threads.
// ---------------------------------------------------------------------------
#define STAGE_BYTES 65536        // Ahi 16K | Alo 16K | Bhi 16K | Blo 16K
#define SMEM_K2 (3 * STAGE_BYTES)

__global__ void __launch_bounds__(256, 1) k2_att_mma(const float* __restrict__ Vv) {
    extern __shared__ char smem[];
    __shared__ float sV[128], sHB[128], attred[128];
    uint32_t sb = smem_u32(smem);

    int tid  = threadIdx.x;
    int wid  = tid >> 5;
    int lane = tid & 31;
    int g    = lane >> 2;      // mma group id
    int tg   = lane & 3;       // thread in group
    int warp_m = wid & 1;      // 0..1
    int warp_n = wid >> 1;     // 0..3

    int bx = blockIdx.x;
    int b     = bx >> 6;
    int stile = (bx >> 2) & 15;
    int htile = bx & 3;
    int s0    = stile * 128;
    int hbase = htile * 128;
    int bb    = b * SDIM;

    if (tid < 128) {
        sV[tid]  = Vv[hbase + tid];
        sHB[tid] = g_hb[b * HDIM + hbase + tid];
        attred[tid] = 0.0f;
    }

    // ---- chunk loader: 64 k-values, 128B rows, XOR-swizzled
    auto load_chunk = [&](int kc, int st) {
        int k0 = kc * 64;
        uint32_t base = sb + (uint32_t)st * STAGE_BYTES;
        #pragma unroll
        for (int j = 0; j < 8; j++) {                // A hi+lo: 2048 x 16B
            int idx = j * 256 + tid;
            int sg  = idx >> 10;
            int rem = idx & 1023;
            int r = rem >> 3, c = rem & 7;
            const __nv_bfloat16* src = (sg ? g_ctx_lo : g_ctx_hi)
                + ((size_t)(bb + s0 + r) * IDIM + k0 + c * 8);
            uint32_t o = (uint32_t)(r * 128 + c * 16);
            CP16(base + (uint32_t)sg * 16384u + (o ^ (uint32_t)((r & 7) << 4)), src);
        }
        #pragma unroll
        for (int j = 0; j < 8; j++) {                // B hi+lo: 2048 x 16B
            int idx = j * 256 + tid;
            int sg  = idx >> 10;
            int rem = idx & 1023;
            int r = rem >> 3, c = rem & 7;
            const __nv_bfloat16* src = (sg ? g_wc_lo : g_wc_hi)
                + ((size_t)(hbase + r) * IDIM + k0 + c * 8);
            uint32_t o = (uint32_t)(r * 128 + c * 16);
            CP16(base + 32768u + (uint32_t)sg * 16384u + (o ^ (uint32_t)((r & 7) << 4)), src);
        }
        CP_COMMIT();
    };

    // ---- per-thread ldmatrix address components
    int arow  = warp_m * 64 + (lane & 15);
    uint32_t akoff = (uint32_t)(lane & 16);          // 0 or 16
    uint32_t axor  = (uint32_t)((lane & 7) << 4);
    int brow  = (lane & 7) + ((lane & 16) >> 1);     // 0..15
    uint32_t bkoff = (uint32_t)(((lane >> 3) & 1) * 16);
    uint32_t bxor  = axor;

    uint32_t aoff[4], boff[2];
    #pragma unroll
    for (int t = 0; t < 4; t++) aoff[t] = (uint32_t)((arow + t * 16) * 128) + akoff;
    #pragma unroll
    for (int p = 0; p < 2; p++) boff[p] = (uint32_t)((warp_n * 32 + p * 16 + brow) * 128) + bkoff;

    float acc[4][4][4];
    #pragma unroll
    for (int t = 0; t < 4; t++)
        #pragma unroll
        for (int n = 0; n < 4; n++)
            #pragma unroll
            for (int c = 0; c < 4; c++) acc[t][n][c] = 0.0f;

    load_chunk(0, 0);
    load_chunk(1, 1);

    #pragma unroll 1
    for (int i = 0; i < 8; i++) {
        if (i + 2 < 8) load_chunk(i + 2, (i + 2) % 3);
        if (i + 2 < 8)      { CP_WAIT(2); }
        else if (i + 1 < 8) { CP_WAIT(1); }
        else                { CP_WAIT(0); }
        __syncthreads();

        uint32_t stb = sb + (uint32_t)(i % 3) * STAGE_BYTES;
        uint32_t Ahi = stb, Alo = stb + 16384u, Bhi = stb + 32768u, Blo = stb + 49152u;

        #pragma unroll
        for (int q = 0; q < 4; q++) {
            uint32_t qb = (uint32_t)(q * 32);
            uint32_t aH[4][4], aL[4][4], bH[2][4], bL[2][4];
            #pragma unroll
            for (int t = 0; t < 4; t++) {
                LDSM4(aH[t], Ahi + ((aoff[t] + qb) ^ axor));
                LDSM4(aL[t], Alo + ((aoff[t] + qb) ^ axor));
            }
            #pragma unroll
            for (int p = 0; p < 2; p++) {
                LDSM4(bH[p], Bhi + ((boff[p] + qb) ^ bxor));
                LDSM4(bL[p], Blo + ((boff[p] + qb) ^ bxor));
            }
            #pragma unroll
            for (int t = 0; t < 4; t++) {
                #pragma unroll
                for (int nt = 0; nt < 4; nt++) {
                    int p  = nt >> 1;
                    int r0 = (nt & 1) * 2;
                    MMA16816(acc[t][nt], aH[t], bH[p][r0], bH[p][r0 + 1]);
                    MMA16816(acc[t][nt], aH[t], bL[p][r0], bL[p][r0 + 1]);
                    MMA16816(acc[t][nt], aL[t], bH[p][r0], bH[p][r0 + 1]);
                }
            }
        }
        __syncthreads();
    }

    // ---- epilogue: att[s] += sum_h V[h]*tanh(acc + hb[h])
    float rowsum[8];
    #pragma unroll
    for (int r = 0; r < 8; r++) rowsum[r] = 0.0f;
    #pragma unroll
    for (int t = 0; t < 4; t++) {
        #pragma unroll
        for (int nt = 0; nt < 4; nt++) {
            int hh = warp_n * 32 + nt * 8 + tg * 2;
            float v0 = sV[hh], v1 = sV[hh + 1];
            float h0 = sHB[hh], h1 = sHB[hh + 1];
            float* c = acc[t][nt];
            rowsum[t * 2 + 0] += v0 * tanhf(c[0] + h0) + v1 * tanhf(c[1] + h1);
            rowsum[t * 2 + 1] += v0 * tanhf(c[2] + h0) + v1 * tanhf(c[3] + h1);
        }
    }
    #pragma unroll
    for (int r = 0; r < 8; r++) {
        float s = rowsum[r];
        s += __shfl_xor_sync(0xffffffffu, s, 1);
        s += __shfl_xor_sync(0xffffffffu, s, 2);
        if (tg == 0) {
            int row = warp_m * 64 + (r >> 1) * 16 + (r & 1) * 8 + g;
            atomicAdd(&attred[row], s);
        }
    }
    __syncthreads();
    if (tid < 128) atomicAdd(&g_att[b * SDIM + s0 + tid], attred[tid]);
}

// ---------------------------------------------------------------------------
// K3: masked softmax over S per batch -> alpha
// ---------------------------------------------------------------------------
__device__ __forceinline__ bool mask_at(const unsigned char* m, int idx, int is_byte) {
    if (is_byte) return m[idx] != 0;
    return ((const int*)m)[idx] != 0;
}

__global__ void k3_softmax(const unsigned char* __restrict__ mraw,
                           float* __restrict__ alpha) {
    __shared__ float red[256];
    int b = blockIdx.x;
    int tid = threadIdx.x;
    int is_byte = g_mask_is_byte;
    const float NEG_INF = __int_as_float(0xff800000);

    float lmax = NEG_INF;
    for (int s = tid; s < SDIM; s += 256)
        if (!mask_at(mraw, b * SDIM + s, is_byte))
            lmax = fmaxf(lmax, g_att[b * SDIM + s]);
    red[tid] = lmax;
    __syncthreads();
    for (int o = 128; o > 0; o >>= 1) {
        if (tid < o) red[tid] = fmaxf(red[tid], red[tid + o]);
        __syncthreads();
    }
    float smax = red[0];
    __syncthreads();

    float lsum = 0.0f;
    for (int s = tid; s < SDIM; s += 256) {
        float e = 0.0f;
        if (!mask_at(mraw, b * SDIM + s, is_byte))
            e = expf(g_att[b * SDIM + s] - smax);
        alpha[b * SDIM + s] = e;
        lsum += e;
    }
    red[tid] = lsum;
    __syncthreads();
    for (int o = 128; o > 0; o >>= 1) {
        if (tid < o) red[tid] += red[tid + o];
        __syncthreads();
    }
    float inv = 1.0f / red[0];
    __syncthreads();

    for (int s = tid; s < SDIM; s += 256)
        alpha[b * SDIM + s] *= inv;
}

// ---------------------------------------------------------------------------
// K4: cbar[b,i] = sum_s alpha[b,s] * context[b,s,i]  (streams 256 MB)
// ---------------------------------------------------------------------------
__global__ void k4_cbar(const float* __restrict__ context,
                        const float* __restrict__ alpha) {
    __shared__ float sal[128];
    int b  = blockIdx.y;
    int s0 = blockIdx.x * 128;
    int i  = threadIdx.x;
    if (i < 128) sal[i] = alpha[b * SDIM + s0 + i];
    __syncthreads();
    const float* cp = context + (size_t)b * SDIM * IDIM + (size_t)s0 * IDIM + i;
    float acc = 0.0f;
    #pragma unroll 4
    for (int s = 0; s < 128; s++) acc += sal[s] * cp[(size_t)s * IDIM];
    atomicAdd(&g_cbar[b * IDIM + i], acc);
}

// ---------------------------------------------------------------------------
// K5: hidden = Wc @ cbar + bc  (coalesced warp-per-row like K1)
// grid(B*4), block(256)
// ---------------------------------------------------------------------------
__global__ void __launch_bounds__(256) k5_out(const float* __restrict__ Wc,
                                              const float* __restrict__ bc,
                                              float* __restrict__ out) {
    __shared__ float sc[IDIM];
    int b  = blockIdx.x >> 2;
    int hq = blockIdx.x & 3;
    int tid = threadIdx.x;
    int wid = tid >> 5, lane = tid & 31;

    sc[tid] = g_cbar[b * IDIM + tid];
    sc[tid + 256] = g_cbar[b * IDIM + tid + 256];
    __syncthreads();

    const float4* s4 = (const float4*)sc;
    #pragma unroll 1
    for (int r = wid; r < 128; r += 8) {
        int h = hq * 128 + r;
        const float4* w4 = (const float4*)(Wc + (size_t)h * IDIM);
        float acc = 0.0f;
        #pragma unroll
        for (int j = 0; j < 4; j++) {
            float4 w = w4[lane + 32 * j];
            float4 s = s4[lane + 32 * j];
            acc += w.x * s.x + w.y * s.y + w.z * s.z + w.w * s.w;
        }
        #pragma unroll
        for (int o = 16; o > 0; o >>= 1) acc += __shfl_xor_sync(0xffffffffu, acc, o);
        if (lane == 0) out[b * HDIM + h] = acc + bc[h];
    }
}

// ---------------------------------------------------------------------------
extern "C" void kernel_launch(void* const* d_in, const int* in_sizes, int n_in,
                              void* d_out, int out_size) {
    const float* inp          = (const float*)d_in[0];
    const float* context      = (const float*)d_in[1];
    const unsigned char* mraw = (const unsigned char*)d_in[2];
    const float* Wl           = (const float*)d_in[3];
    const float* bl           = (const float*)d_in[4];
    const float* Wc           = (const float*)d_in[5];
    const float* bc           = (const float*)d_in[6];
    const float* Vv           = (const float*)d_in[7];

    float* out    = (float*)d_out;
    float* hidden = out;                   // [B, HID]
    float* alpha  = out + BDIM * HDIM;     // [B, S]

    cudaFuncSetAttribute(k2_att_mma, cudaFuncAttributeMaxDynamicSharedMemorySize, SMEM_K2);

    __nv_bfloat16 *ctx_hi, *ctx_lo, *wc_hi, *wc_lo;
    cudaGetSymbolAddress((void**)&ctx_hi, g_ctx_hi);
    cudaGetSymbolAddress((void**)&ctx_lo, g_ctx_lo);
    cudaGetSymbolAddress((void**)&wc_hi, g_wc_hi);
    cudaGetSymbolAddress((void**)&wc_lo, g_wc_lo);

    k0_detect<<<1, 256>>>(mraw);
    int n4c = BDIM * SDIM * IDIM / 4;
    k_conv<<<n4c / 256, 256>>>(context, ctx_hi, ctx_lo, n4c);
    int n4w = HDIM * IDIM / 4;
    k_conv<<<n4w / 256, 256>>>(Wc, wc_hi, wc_lo, n4w);
    k1_hb<<<BDIM * 4, 256>>>(inp, Wl, bl, bc);
    k2_att_mma<<<BDIM * 16 * 4, 256, SMEM_K2>>>(Vv);
    k3_softmax<<<BDIM, 256>>>(mraw, alpha);
    k4_cbar<<<dim3(SDIM / 128, BDIM), 512>>>(context, alpha);
    k5_out<<<BDIM * 4, 256>>>(Wc, bc, hidden);
}